// round 14
// baseline (speedup 1.0000x reference)
#include <cuda_runtime.h>
#include <cuda_fp16.h>
#include <cstdint>

#define N_NODES 100000
#define N_EDGES 1600000
#define F_IN    128
#define HDIM    64
#define TILE_N  32
#define NTH     256
#define NUM_TILES (N_NODES / TILE_N)   // 3125, exact
#define SCAN_BLK 1024
#define NBLK ((N_NODES + SCAN_BLK - 1) / SCAN_BLK)   // 98
#define WSTR 66                        // Wbuf row stride (words)

// ---------------- device scratch (static: no allocation allowed) ----------------
__device__ float  g_Kf[N_NODES * HDIM];
__device__ __half g_QVh[N_NODES * 2 * HDIM];   // interleaved: q pair / v pair per 4-feat group
__device__ float  g_Sk[N_NODES * HDIM];
__device__ int    g_counts[N_NODES];
__device__ int    g_rowstart[N_NODES + 1];
__device__ int    g_cursor[N_NODES];
__device__ int    g_sorted_src[N_EDGES];
__device__ int    g_blocksums[128];
__device__ int    g_is64;

// ---------------- f32x2 packed helpers ----------------
__device__ __forceinline__ unsigned long long pk2(float lo, float hi) {
    unsigned long long r;
    asm("mov.b64 %0, {%1, %2};" : "=l"(r) : "r"(__float_as_uint(lo)), "r"(__float_as_uint(hi)));
    return r;
}
__device__ __forceinline__ float2 unpk(unsigned long long v) {
    unsigned lo, hi;
    asm("mov.b64 {%0, %1}, %2;" : "=r"(lo), "=r"(hi) : "l"(v));
    return make_float2(__uint_as_float(lo), __uint_as_float(hi));
}
__device__ __forceinline__ void ffma2(unsigned long long& acc,
                                      unsigned long long a, unsigned long long b) {
    asm("fma.rn.f32x2 %0, %1, %2, %0;" : "+l"(acc) : "l"(a), "l"(b));
}

// ---------------- init: dtype probe (block 0) + zero counts ----------------
__global__ void init_kernel(const void* __restrict__ ei)
{
    int gi = blockIdx.x * 256 + threadIdx.x;
    if (blockIdx.x == 0) {
        const unsigned long long* p = (const unsigned long long*)ei;
        int bad = (p[threadIdx.x] >> 32) != 0ull;
        bad = __syncthreads_or(bad);
        if (threadIdx.x == 0) g_is64 = !bad;
    }
    if (gi < N_NODES) g_counts[gi] = 0;
}

__device__ __forceinline__ int edge_at(const void* __restrict__ ei, int pos, int is64)
{
    if (is64) return (int)((const long long*)ei)[pos];
    return ((const int*)ei)[pos];
}

// ---------------- fused node kernel ----------------
struct SmemT {
    __align__(16) float Wbuf[64 * WSTR];
    __align__(16) float Xbuf[TILE_N * 132];   // reused as H2 (stride 132)
    __align__(16) float H1buf[TILE_N * 68];
    float biasS[6 * 64];
};

__device__ __forceinline__ void stage_w(float* __restrict__ Wbuf,
                                        const float* __restrict__ W,
                                        int ldw, int kofs)
{
    #pragma unroll
    for (int idx = threadIdx.x; idx < 64 * 64; idx += NTH) {
        int f = idx >> 6, k = idx & 63;
        int row = ((f & 3) << 4) | (f >> 2);       // fi*16 + tf
        Wbuf[row * WSTR + k] = W[f * ldw + kofs + k];
    }
}

__device__ __forceinline__ void gemm_kp(const float* __restrict__ In, int ldin, int kbase,
                                        const float* __restrict__ Wbuf,
                                        unsigned long long acc[2][4], int tf, int tn)
{
    const float* in0 = In + (tn * 2 + 0) * ldin + kbase;
    const float* in1 = In + (tn * 2 + 1) * ldin + kbase;
    const float* w0 = Wbuf + (0 * 16 + tf) * WSTR;
    const float* w1 = Wbuf + (1 * 16 + tf) * WSTR;
    const float* w2 = Wbuf + (2 * 16 + tf) * WSTR;
    const float* w3 = Wbuf + (3 * 16 + tf) * WSTR;
    #pragma unroll 8
    for (int kp = 0; kp < 32; kp++) {
        unsigned long long xp0 = *(const unsigned long long*)&in0[kp * 2];
        unsigned long long xp1 = *(const unsigned long long*)&in1[kp * 2];
        unsigned long long wa = *(const unsigned long long*)&w0[kp * 2];
        unsigned long long wb = *(const unsigned long long*)&w1[kp * 2];
        unsigned long long wc = *(const unsigned long long*)&w2[kp * 2];
        unsigned long long wd = *(const unsigned long long*)&w3[kp * 2];
        ffma2(acc[0][0], xp0, wa); ffma2(acc[0][1], xp0, wb);
        ffma2(acc[0][2], xp0, wc); ffma2(acc[0][3], xp0, wd);
        ffma2(acc[1][0], xp1, wa); ffma2(acc[1][1], xp1, wb);
        ffma2(acc[1][2], xp1, wc); ffma2(acc[1][3], xp1, wd);
    }
}

__device__ __forceinline__ void init_kp(const float* __restrict__ biasS, int boff,
                                        unsigned long long acc[2][4], int tf)
{
    #pragma unroll
    for (int fi = 0; fi < 4; fi++) {
        unsigned long long b = pk2(biasS[boff + tf * 4 + fi], 0.0f);
        acc[0][fi] = b; acc[1][fi] = b;
    }
}

__device__ __forceinline__ void reduce_kp(unsigned long long acc[2][4], float r[2][4])
{
    #pragma unroll
    for (int ni = 0; ni < 2; ni++)
        #pragma unroll
        for (int fi = 0; fi < 4; fi++) {
            float2 p = unpk(acc[ni][fi]);
            r[ni][fi] = p.x + p.y;
        }
}

__global__ void __launch_bounds__(NTH)
node_kernel(const float* __restrict__ x,
            const float* __restrict__ W1, const float* __restrict__ b1,
            const float* __restrict__ W2, const float* __restrict__ b2,
            const float* __restrict__ Wk, const float* __restrict__ bk,
            const float* __restrict__ Wq, const float* __restrict__ bq,
            const float* __restrict__ Wv, const float* __restrict__ bv,
            const float* __restrict__ Ws, const float* __restrict__ bgate,
            const void* __restrict__ ei)
{
    __shared__ SmemT sm;
    const int tid = threadIdx.x;
    const int nb  = blockIdx.x * TILE_N;
    const int tf  = tid & 15;
    const int tn  = tid >> 4;

    for (int idx = tid; idx < TILE_N * F_IN; idx += NTH) {
        int n = idx >> 7, k = idx & 127;
        sm.Xbuf[n * 132 + k] = x[(nb + n) * F_IN + k];
    }
    if (tid < HDIM) {
        sm.biasS[tid]       = b1[tid];
        sm.biasS[64 + tid]  = b2[tid];
        sm.biasS[128 + tid] = bk[tid];
        sm.biasS[192 + tid] = bq[tid];
        sm.biasS[256 + tid] = bv[tid];
        sm.biasS[320 + tid] = bgate[tid];
    }
    stage_w(sm.Wbuf, W1, F_IN, 0);
    __syncthreads();

    unsigned long long acc[2][4];
    float r[2][4];

    // layer 1: relu(x @ W1^T + b1), K=128 in two chunks
    init_kp(sm.biasS, 0, acc, tf);
    gemm_kp(sm.Xbuf, 132, 0, sm.Wbuf, acc, tf, tn);
    __syncthreads();
    stage_w(sm.Wbuf, W1, F_IN, 64);
    __syncthreads();
    gemm_kp(sm.Xbuf, 132, 64, sm.Wbuf, acc, tf, tn);
    reduce_kp(acc, r);
    #pragma unroll
    for (int ni = 0; ni < 2; ni++) {
        float4 v = make_float4(fmaxf(r[ni][0], 0.f), fmaxf(r[ni][1], 0.f),
                               fmaxf(r[ni][2], 0.f), fmaxf(r[ni][3], 0.f));
        *(float4*)&sm.H1buf[(tn * 2 + ni) * 68 + tf * 4] = v;
    }
    __syncthreads();

    // layer 2 -> H2 aliases Xbuf (stride 132)
    stage_w(sm.Wbuf, W2, HDIM, 0);
    __syncthreads();
    init_kp(sm.biasS, 64, acc, tf);
    gemm_kp(sm.H1buf, 68, 0, sm.Wbuf, acc, tf, tn);
    reduce_kp(acc, r);
    float* H2 = sm.Xbuf;
    #pragma unroll
    for (int ni = 0; ni < 2; ni++)
        *(float4*)&H2[(tn * 2 + ni) * 132 + tf * 4] =
            make_float4(r[ni][0], r[ni][1], r[ni][2], r[ni][3]);
    __syncthreads();

    // ---- heads ----
    // k (fp32)
    stage_w(sm.Wbuf, Wk, HDIM, 0);
    __syncthreads();
    init_kp(sm.biasS, 128, acc, tf);
    gemm_kp(H2, 132, 0, sm.Wbuf, acc, tf, tn);
    reduce_kp(acc, r);
    #pragma unroll
    for (int ni = 0; ni < 2; ni++)
        *(float4*)&g_Kf[(nb + tn * 2 + ni) * HDIM + tf * 4] =
            make_float4(r[ni][0], r[ni][1], r[ni][2], r[ni][3]);
    __syncthreads();

    // q (fp16, interleaved at QV[node][tf*8 .. +3])
    stage_w(sm.Wbuf, Wq, HDIM, 0);
    __syncthreads();
    init_kp(sm.biasS, 192, acc, tf);
    gemm_kp(H2, 132, 0, sm.Wbuf, acc, tf, tn);
    reduce_kp(acc, r);
    #pragma unroll
    for (int ni = 0; ni < 2; ni++) {
        __half2 h0 = __floats2half2_rn(r[ni][0], r[ni][1]);
        __half2 h1 = __floats2half2_rn(r[ni][2], r[ni][3]);
        uint2 pk; pk.x = *(unsigned*)&h0; pk.y = *(unsigned*)&h1;
        *(uint2*)&g_QVh[(nb + tn * 2 + ni) * 128 + tf * 8] = pk;
    }
    __syncthreads();

    // v (fp16, interleaved at QV[node][tf*8+4 .. +7])
    stage_w(sm.Wbuf, Wv, HDIM, 0);
    __syncthreads();
    init_kp(sm.biasS, 256, acc, tf);
    gemm_kp(H2, 132, 0, sm.Wbuf, acc, tf, tn);
    reduce_kp(acc, r);
    #pragma unroll
    for (int ni = 0; ni < 2; ni++) {
        __half2 h0 = __floats2half2_rn(r[ni][0], r[ni][1]);
        __half2 h1 = __floats2half2_rn(r[ni][2], r[ni][3]);
        uint2 pk; pk.x = *(unsigned*)&h0; pk.y = *(unsigned*)&h1;
        *(uint2*)&g_QVh[(nb + tn * 2 + ni) * 128 + tf * 8 + 4] = pk;
    }
    __syncthreads();

    // skip (fp32)
    stage_w(sm.Wbuf, Ws, HDIM, 0);
    __syncthreads();
    init_kp(sm.biasS, 320, acc, tf);
    gemm_kp(H2, 132, 0, sm.Wbuf, acc, tf, tn);
    reduce_kp(acc, r);
    #pragma unroll
    for (int ni = 0; ni < 2; ni++)
        *(float4*)&g_Sk[(nb + tn * 2 + ni) * HDIM + tf * 4] =
            make_float4(r[ni][0], r[ni][1], r[ni][2], r[ni][3]);

    // fused histogram tail
    int is64 = g_is64;
    int base = blockIdx.x * NTH + tid;
    #pragma unroll
    for (int rr = 0; rr < 2; rr++) {
        int e = base + rr * (NUM_TILES * NTH);
        if (e < N_EDGES) {
            int d = edge_at(ei, N_EDGES + e, is64);
            if ((unsigned)d < (unsigned)N_NODES)
                atomicAdd(&g_counts[d], 1);
        }
    }
}

// ---------------- CSR build ----------------
__global__ void scan_blocks_kernel()
{
    __shared__ int wsums[32];
    const int tid  = threadIdx.x;
    const int lane = tid & 31;
    const int wid  = tid >> 5;
    int i = blockIdx.x * SCAN_BLK + tid;
    int v = (i < N_NODES) ? g_counts[i] : 0;
    int s = v;
    #pragma unroll
    for (int o = 1; o < 32; o <<= 1) {
        int t = __shfl_up_sync(0xffffffffu, s, o);
        if (lane >= o) s += t;
    }
    if (lane == 31) wsums[wid] = s;
    __syncthreads();
    if (wid == 0) {
        int ws = wsums[lane];
        #pragma unroll
        for (int o = 1; o < 32; o <<= 1) {
            int t = __shfl_up_sync(0xffffffffu, ws, o);
            if (lane >= o) ws += t;
        }
        wsums[lane] = ws;
    }
    __syncthreads();
    int off = (wid > 0) ? wsums[wid - 1] : 0;
    int excl = s - v + off;
    if (i < N_NODES) g_rowstart[i] = excl;
    if (tid == SCAN_BLK - 1) g_blocksums[blockIdx.x] = excl + v;
}

// each block redundantly reduces its prefix of block sums, then applies offsets
__global__ void final_scan_kernel()
{
    __shared__ int offset_s;
    const int tid = threadIdx.x;
    if (tid < 32) {
        int s = 0;
        for (int b = tid; b < (int)blockIdx.x; b += 32) s += g_blocksums[b];
        #pragma unroll
        for (int o = 16; o > 0; o >>= 1) s += __shfl_down_sync(0xffffffffu, s, o);
        if (tid == 0) offset_s = s;
    }
    __syncthreads();
    int i = blockIdx.x * SCAN_BLK + tid;
    if (i < N_NODES) {
        int r = g_rowstart[i] + offset_s;
        g_rowstart[i] = r;
        g_cursor[i]   = r;
    }
    if (blockIdx.x == NBLK - 1 && tid == 0)
        g_rowstart[N_NODES] = offset_s + g_blocksums[NBLK - 1];
}

__global__ void scatter_kernel(const void* __restrict__ ei)
{
    int e = blockIdx.x * blockDim.x + threadIdx.x;
    if (e < N_EDGES) {
        int is64 = g_is64;
        int s = edge_at(ei, e, is64);
        int d = edge_at(ei, N_EDGES + e, is64);
        if ((unsigned)d < (unsigned)N_NODES && (unsigned)s < (unsigned)N_NODES) {
            int pos = atomicAdd(&g_cursor[d], 1);
            if ((unsigned)pos < (unsigned)N_EDGES)
                g_sorted_src[pos] = s;
        }
    }
}

// ---------------- aggregate + fused scorer ----------------
// 2 nodes/warp, one LDG.128 per lane per edge (QV interleaved), 8-edge pipeline.
__device__ __forceinline__ float gatef(float q, float kh)
{
    float t;
    asm("tanh.approx.f32 %0, %1;" : "=f"(t) : "f"(fmaf(q, 0.5f, kh)));
    return fmaf(t, 0.5f, 0.5f);
}

__global__ void aggregate_kernel(const float* __restrict__ Wsc,
                                 const float* __restrict__ bsc,
                                 float* __restrict__ score)
{
    int gwarp = (blockIdx.x * blockDim.x + threadIdx.x) >> 5;
    int lane  = threadIdx.x & 31;
    int half  = lane >> 4;
    int hl    = lane & 15;
    int i = gwarp * 2 + half;
    if (i >= N_NODES) return;
    unsigned hmask = half ? 0xffff0000u : 0x0000ffffu;

    float4 kh = *(const float4*)&g_Kf[i * HDIM + hl * 4];
    kh.x *= 0.5f; kh.y *= 0.5f; kh.z *= 0.5f; kh.w *= 0.5f;
    float ax = 0.f, ay = 0.f, az = 0.f, aw = 0.f;

    const int qvofs = hl * 8;
    int start = g_rowstart[i];
    int end   = g_rowstart[i + 1];
    for (int b = start; b < end; b += 16) {
        int m = end - b; if (m > 16) m = 16;
        int j = g_sorted_src[b + ((hl < m) ? hl : 0)];
        for (int t0 = 0; t0 < m; t0 += 8) {
            uint4 qv[8];
            #pragma unroll
            for (int u = 0; u < 8; u++) {
                int t  = t0 + u;
                int tc = (t < m) ? t : 0;
                int jj = __shfl_sync(hmask, j, half * 16 + tc);
                qv[u] = *(const uint4*)&g_QVh[jj * 128 + qvofs];
                if (t >= m) { qv[u].z = 0u; qv[u].w = 0u; }   // zero v kills padding
            }
            #pragma unroll
            for (int u = 0; u < 8; u++) {
                float2 q01 = __half22float2(*(const __half2*)&qv[u].x);
                float2 q23 = __half22float2(*(const __half2*)&qv[u].y);
                float2 v01 = __half22float2(*(const __half2*)&qv[u].z);
                float2 v23 = __half22float2(*(const __half2*)&qv[u].w);
                ax = fmaf(gatef(q01.x, kh.x), v01.x, ax);
                ay = fmaf(gatef(q01.y, kh.y), v01.y, ay);
                az = fmaf(gatef(q23.x, kh.z), v23.x, az);
                aw = fmaf(gatef(q23.y, kh.w), v23.y, aw);
            }
        }
    }

    float4 sk = *(const float4*)&g_Sk[i * HDIM + hl * 4];
    ax += sk.x; ay += sk.y; az += sk.z; aw += sk.w;

    float4 w = *(const float4*)&Wsc[hl * 4];
    float p = ax * w.x + ay * w.y + az * w.z + aw * w.w;
    #pragma unroll
    for (int o = 8; o > 0; o >>= 1) p += __shfl_down_sync(hmask, p, o, 16);
    if (hl == 0) score[i] = p + bsc[0];
}

// ---------------- launch (kernel launches ONLY) ----------------
extern "C" void kernel_launch(void* const* d_in, const int* in_sizes, int n_in,
                              void* d_out, int out_size)
{
    const float* x     = (const float*)d_in[0];
    const void*  ei    = d_in[1];
    const float* W1    = (const float*)d_in[2];
    const float* b1    = (const float*)d_in[3];
    const float* W2    = (const float*)d_in[4];
    const float* b2    = (const float*)d_in[5];
    const float* Wk    = (const float*)d_in[6];
    const float* bk    = (const float*)d_in[7];
    const float* Wq    = (const float*)d_in[8];
    const float* bq    = (const float*)d_in[9];
    const float* Wv    = (const float*)d_in[10];
    const float* bv    = (const float*)d_in[11];
    const float* Ws    = (const float*)d_in[12];
    const float* bgate = (const float*)d_in[13];
    const float* Wsc   = (const float*)d_in[14];
    const float* bsc   = (const float*)d_in[15];
    float* score = (float*)d_out;

    init_kernel<<<(N_NODES + 255) / 256, 256>>>(ei);   // dtype probe + zero counts

    node_kernel<<<NUM_TILES, NTH>>>(x, W1, b1, W2, b2, Wk, bk,
                                    Wq, bq, Wv, bv, Ws, bgate, ei);

    scan_blocks_kernel<<<NBLK, SCAN_BLK>>>();
    final_scan_kernel<<<NBLK, SCAN_BLK>>>();
    scatter_kernel<<<(N_EDGES + 255) / 256, 256>>>(ei);

    int agg_blocks = (N_NODES / 2 * 32) / 256;   // 6250, exact
    aggregate_kernel<<<agg_blocks, 256>>>(Wsc, bsc, score);
}

// round 16
// speedup vs baseline: 1.0614x; 1.0614x over previous
#include <cuda_runtime.h>
#include <cuda_fp16.h>
#include <cstdint>

#define N_NODES 100000
#define N_EDGES 1600000
#define F_IN    128
#define HDIM    64
#define TILE_N  32
#define NTH     256
#define NUM_TILES (N_NODES / TILE_N)   // 3125, exact
#define SCAN_BLK 1024
#define NBLK ((N_NODES + SCAN_BLK - 1) / SCAN_BLK)   // 98
#define WSTR 66                        // Wbuf row stride (words)

// ---------------- device scratch (static: no allocation allowed) ----------------
__device__ float  g_Kf[N_NODES * HDIM];
__device__ __half g_Qh[N_NODES * HDIM];
__device__ __half g_Vh[N_NODES * HDIM];
__device__ float  g_Sk[N_NODES * HDIM];
__device__ int    g_counts[N_NODES];
__device__ int    g_rowstart[N_NODES + 1];
__device__ int    g_cursor[N_NODES];
__device__ int    g_sorted_src[N_EDGES];
__device__ int    g_blocksums[128];
__device__ int    g_is64;

// ---------------- f32x2 packed helpers ----------------
__device__ __forceinline__ unsigned long long pk2(float lo, float hi) {
    unsigned long long r;
    asm("mov.b64 %0, {%1, %2};" : "=l"(r) : "r"(__float_as_uint(lo)), "r"(__float_as_uint(hi)));
    return r;
}
__device__ __forceinline__ float2 unpk(unsigned long long v) {
    unsigned lo, hi;
    asm("mov.b64 {%0, %1}, %2;" : "=r"(lo), "=r"(hi) : "l"(v));
    return make_float2(__uint_as_float(lo), __uint_as_float(hi));
}
__device__ __forceinline__ void ffma2(unsigned long long& acc,
                                      unsigned long long a, unsigned long long b) {
    asm("fma.rn.f32x2 %0, %1, %2, %0;" : "+l"(acc) : "l"(a), "l"(b));
}

// ---------------- init: dtype probe (block 0) + zero counts ----------------
__global__ void init_kernel(const void* __restrict__ ei)
{
    int gi = blockIdx.x * 256 + threadIdx.x;
    if (blockIdx.x == 0) {
        const unsigned long long* p = (const unsigned long long*)ei;
        int bad = (p[threadIdx.x] >> 32) != 0ull;
        bad = __syncthreads_or(bad);
        if (threadIdx.x == 0) g_is64 = !bad;
    }
    if (gi < N_NODES) g_counts[gi] = 0;
}

__device__ __forceinline__ int edge_at(const void* __restrict__ ei, int pos, int is64)
{
    if (is64) return (int)((const long long*)ei)[pos];
    return ((const int*)ei)[pos];
}

// ---------------- fused node kernel ----------------
struct SmemT {
    __align__(16) float Wbuf[64 * WSTR];
    __align__(16) float Xbuf[TILE_N * 132];   // reused as H2 (stride 132)
    __align__(16) float H1buf[TILE_N * 68];
    float biasS[6 * 64];
};

__device__ __forceinline__ void stage_w(float* __restrict__ Wbuf,
                                        const float* __restrict__ W,
                                        int ldw, int kofs)
{
    #pragma unroll
    for (int idx = threadIdx.x; idx < 64 * 64; idx += NTH) {
        int f = idx >> 6, k = idx & 63;
        int row = ((f & 3) << 4) | (f >> 2);       // fi*16 + tf
        Wbuf[row * WSTR + k] = W[f * ldw + kofs + k];
    }
}

__device__ __forceinline__ void gemm_kp(const float* __restrict__ In, int ldin, int kbase,
                                        const float* __restrict__ Wbuf,
                                        unsigned long long acc[2][4], int tf, int tn)
{
    const float* in0 = In + (tn * 2 + 0) * ldin + kbase;
    const float* in1 = In + (tn * 2 + 1) * ldin + kbase;
    const float* w0 = Wbuf + (0 * 16 + tf) * WSTR;
    const float* w1 = Wbuf + (1 * 16 + tf) * WSTR;
    const float* w2 = Wbuf + (2 * 16 + tf) * WSTR;
    const float* w3 = Wbuf + (3 * 16 + tf) * WSTR;
    #pragma unroll 8
    for (int kp = 0; kp < 32; kp++) {
        unsigned long long xp0 = *(const unsigned long long*)&in0[kp * 2];
        unsigned long long xp1 = *(const unsigned long long*)&in1[kp * 2];
        unsigned long long wa = *(const unsigned long long*)&w0[kp * 2];
        unsigned long long wb = *(const unsigned long long*)&w1[kp * 2];
        unsigned long long wc = *(const unsigned long long*)&w2[kp * 2];
        unsigned long long wd = *(const unsigned long long*)&w3[kp * 2];
        ffma2(acc[0][0], xp0, wa); ffma2(acc[0][1], xp0, wb);
        ffma2(acc[0][2], xp0, wc); ffma2(acc[0][3], xp0, wd);
        ffma2(acc[1][0], xp1, wa); ffma2(acc[1][1], xp1, wb);
        ffma2(acc[1][2], xp1, wc); ffma2(acc[1][3], xp1, wd);
    }
}

__device__ __forceinline__ void init_kp(const float* __restrict__ biasS, int boff,
                                        unsigned long long acc[2][4], int tf)
{
    #pragma unroll
    for (int fi = 0; fi < 4; fi++) {
        unsigned long long b = pk2(biasS[boff + tf * 4 + fi], 0.0f);
        acc[0][fi] = b; acc[1][fi] = b;
    }
}

__device__ __forceinline__ void reduce_kp(unsigned long long acc[2][4], float r[2][4])
{
    #pragma unroll
    for (int ni = 0; ni < 2; ni++)
        #pragma unroll
        for (int fi = 0; fi < 4; fi++) {
            float2 p = unpk(acc[ni][fi]);
            r[ni][fi] = p.x + p.y;
        }
}

__global__ void __launch_bounds__(NTH)
node_kernel(const float* __restrict__ x,
            const float* __restrict__ W1, const float* __restrict__ b1,
            const float* __restrict__ W2, const float* __restrict__ b2,
            const float* __restrict__ Wk, const float* __restrict__ bk,
            const float* __restrict__ Wq, const float* __restrict__ bq,
            const float* __restrict__ Wv, const float* __restrict__ bv,
            const float* __restrict__ Ws, const float* __restrict__ bgate,
            const void* __restrict__ ei)
{
    __shared__ SmemT sm;
    const int tid = threadIdx.x;
    const int nb  = blockIdx.x * TILE_N;
    const int tf  = tid & 15;
    const int tn  = tid >> 4;

    for (int idx = tid; idx < TILE_N * F_IN; idx += NTH) {
        int n = idx >> 7, k = idx & 127;
        sm.Xbuf[n * 132 + k] = x[(nb + n) * F_IN + k];
    }
    if (tid < HDIM) {
        sm.biasS[tid]       = b1[tid];
        sm.biasS[64 + tid]  = b2[tid];
        sm.biasS[128 + tid] = bk[tid];
        sm.biasS[192 + tid] = bq[tid];
        sm.biasS[256 + tid] = bv[tid];
        sm.biasS[320 + tid] = bgate[tid];
    }
    stage_w(sm.Wbuf, W1, F_IN, 0);
    __syncthreads();

    unsigned long long acc[2][4];
    float r[2][4];

    // layer 1: relu(x @ W1^T + b1), K=128 in two chunks
    init_kp(sm.biasS, 0, acc, tf);
    gemm_kp(sm.Xbuf, 132, 0, sm.Wbuf, acc, tf, tn);
    __syncthreads();
    stage_w(sm.Wbuf, W1, F_IN, 64);
    __syncthreads();
    gemm_kp(sm.Xbuf, 132, 64, sm.Wbuf, acc, tf, tn);
    reduce_kp(acc, r);
    #pragma unroll
    for (int ni = 0; ni < 2; ni++) {
        float4 v = make_float4(fmaxf(r[ni][0], 0.f), fmaxf(r[ni][1], 0.f),
                               fmaxf(r[ni][2], 0.f), fmaxf(r[ni][3], 0.f));
        *(float4*)&sm.H1buf[(tn * 2 + ni) * 68 + tf * 4] = v;
    }
    __syncthreads();

    // layer 2 -> H2 aliases Xbuf (stride 132)
    stage_w(sm.Wbuf, W2, HDIM, 0);
    __syncthreads();
    init_kp(sm.biasS, 64, acc, tf);
    gemm_kp(sm.H1buf, 68, 0, sm.Wbuf, acc, tf, tn);
    reduce_kp(acc, r);
    float* H2 = sm.Xbuf;
    #pragma unroll
    for (int ni = 0; ni < 2; ni++)
        *(float4*)&H2[(tn * 2 + ni) * 132 + tf * 4] =
            make_float4(r[ni][0], r[ni][1], r[ni][2], r[ni][3]);
    __syncthreads();

    // ---- heads ----
    // k (fp32)
    stage_w(sm.Wbuf, Wk, HDIM, 0);
    __syncthreads();
    init_kp(sm.biasS, 128, acc, tf);
    gemm_kp(H2, 132, 0, sm.Wbuf, acc, tf, tn);
    reduce_kp(acc, r);
    #pragma unroll
    for (int ni = 0; ni < 2; ni++)
        *(float4*)&g_Kf[(nb + tn * 2 + ni) * HDIM + tf * 4] =
            make_float4(r[ni][0], r[ni][1], r[ni][2], r[ni][3]);
    __syncthreads();

    // q (fp16)
    stage_w(sm.Wbuf, Wq, HDIM, 0);
    __syncthreads();
    init_kp(sm.biasS, 192, acc, tf);
    gemm_kp(H2, 132, 0, sm.Wbuf, acc, tf, tn);
    reduce_kp(acc, r);
    #pragma unroll
    for (int ni = 0; ni < 2; ni++) {
        __half2 h0 = __floats2half2_rn(r[ni][0], r[ni][1]);
        __half2 h1 = __floats2half2_rn(r[ni][2], r[ni][3]);
        uint2 pk; pk.x = *(unsigned*)&h0; pk.y = *(unsigned*)&h1;
        *(uint2*)&g_Qh[(nb + tn * 2 + ni) * HDIM + tf * 4] = pk;
    }
    __syncthreads();

    // v (fp16)
    stage_w(sm.Wbuf, Wv, HDIM, 0);
    __syncthreads();
    init_kp(sm.biasS, 256, acc, tf);
    gemm_kp(H2, 132, 0, sm.Wbuf, acc, tf, tn);
    reduce_kp(acc, r);
    #pragma unroll
    for (int ni = 0; ni < 2; ni++) {
        __half2 h0 = __floats2half2_rn(r[ni][0], r[ni][1]);
        __half2 h1 = __floats2half2_rn(r[ni][2], r[ni][3]);
        uint2 pk; pk.x = *(unsigned*)&h0; pk.y = *(unsigned*)&h1;
        *(uint2*)&g_Vh[(nb + tn * 2 + ni) * HDIM + tf * 4] = pk;
    }
    __syncthreads();

    // skip (fp32)
    stage_w(sm.Wbuf, Ws, HDIM, 0);
    __syncthreads();
    init_kp(sm.biasS, 320, acc, tf);
    gemm_kp(H2, 132, 0, sm.Wbuf, acc, tf, tn);
    reduce_kp(acc, r);
    #pragma unroll
    for (int ni = 0; ni < 2; ni++)
        *(float4*)&g_Sk[(nb + tn * 2 + ni) * HDIM + tf * 4] =
            make_float4(r[ni][0], r[ni][1], r[ni][2], r[ni][3]);

    // fused histogram tail
    int is64 = g_is64;
    int base = blockIdx.x * NTH + tid;
    #pragma unroll
    for (int rr = 0; rr < 2; rr++) {
        int e = base + rr * (NUM_TILES * NTH);
        if (e < N_EDGES) {
            int d = edge_at(ei, N_EDGES + e, is64);
            if ((unsigned)d < (unsigned)N_NODES)
                atomicAdd(&g_counts[d], 1);
        }
    }
}

// ---------------- CSR build ----------------
__global__ void scan_blocks_kernel()
{
    __shared__ int wsums[32];
    const int tid  = threadIdx.x;
    const int lane = tid & 31;
    const int wid  = tid >> 5;
    int i = blockIdx.x * SCAN_BLK + tid;
    int v = (i < N_NODES) ? g_counts[i] : 0;
    int s = v;
    #pragma unroll
    for (int o = 1; o < 32; o <<= 1) {
        int t = __shfl_up_sync(0xffffffffu, s, o);
        if (lane >= o) s += t;
    }
    if (lane == 31) wsums[wid] = s;
    __syncthreads();
    if (wid == 0) {
        int ws = wsums[lane];
        #pragma unroll
        for (int o = 1; o < 32; o <<= 1) {
            int t = __shfl_up_sync(0xffffffffu, ws, o);
            if (lane >= o) ws += t;
        }
        wsums[lane] = ws;
    }
    __syncthreads();
    int off = (wid > 0) ? wsums[wid - 1] : 0;
    int excl = s - v + off;
    if (i < N_NODES) g_rowstart[i] = excl;
    if (tid == SCAN_BLK - 1) g_blocksums[blockIdx.x] = excl + v;
}

// each block redundantly reduces its prefix of block sums, then applies offsets
__global__ void final_scan_kernel()
{
    __shared__ int offset_s;
    const int tid = threadIdx.x;
    if (tid < 32) {
        int s = 0;
        for (int b = tid; b < (int)blockIdx.x; b += 32) s += g_blocksums[b];
        #pragma unroll
        for (int o = 16; o > 0; o >>= 1) s += __shfl_down_sync(0xffffffffu, s, o);
        if (tid == 0) offset_s = s;
    }
    __syncthreads();
    int i = blockIdx.x * SCAN_BLK + tid;
    if (i < N_NODES) {
        int r = g_rowstart[i] + offset_s;
        g_rowstart[i] = r;
        g_cursor[i]   = r;
    }
    if (blockIdx.x == NBLK - 1 && tid == 0)
        g_rowstart[N_NODES] = offset_s + g_blocksums[NBLK - 1];
}

__global__ void scatter_kernel(const void* __restrict__ ei)
{
    int e = blockIdx.x * blockDim.x + threadIdx.x;
    if (e < N_EDGES) {
        int is64 = g_is64;
        int s = edge_at(ei, e, is64);
        int d = edge_at(ei, N_EDGES + e, is64);
        if ((unsigned)d < (unsigned)N_NODES && (unsigned)s < (unsigned)N_NODES) {
            int pos = atomicAdd(&g_cursor[d], 1);
            if ((unsigned)pos < (unsigned)N_EDGES)
                g_sorted_src[pos] = s;
        }
    }
}

// ---------------- aggregate + fused scorer (R11-proven form) ----------------
// 2 nodes/warp, separate LDG.64 q/v gathers (cross-LDG wavefronts), 4-edge pipeline.
__device__ __forceinline__ float gatef(float q, float kh)
{
    float t;
    asm("tanh.approx.f32 %0, %1;" : "=f"(t) : "f"(fmaf(q, 0.5f, kh)));
    return fmaf(t, 0.5f, 0.5f);
}

__global__ void aggregate_kernel(const float* __restrict__ Wsc,
                                 const float* __restrict__ bsc,
                                 float* __restrict__ score)
{
    int gwarp = (blockIdx.x * blockDim.x + threadIdx.x) >> 5;
    int lane  = threadIdx.x & 31;
    int half  = lane >> 4;
    int hl    = lane & 15;
    int i = gwarp * 2 + half;
    if (i >= N_NODES) return;
    unsigned hmask = half ? 0xffff0000u : 0x0000ffffu;

    float4 kh = *(const float4*)&g_Kf[i * HDIM + hl * 4];
    kh.x *= 0.5f; kh.y *= 0.5f; kh.z *= 0.5f; kh.w *= 0.5f;
    float ax = 0.f, ay = 0.f, az = 0.f, aw = 0.f;

    int start = g_rowstart[i];
    int end   = g_rowstart[i + 1];
    for (int b = start; b < end; b += 16) {
        int m = end - b; if (m > 16) m = 16;
        int j = g_sorted_src[b + ((hl < m) ? hl : 0)];
        for (int t0 = 0; t0 < m; t0 += 4) {
            uint2 qr[4], vr[4];
            #pragma unroll
            for (int u = 0; u < 4; u++) {
                int t  = t0 + u;
                int tc = (t < m) ? t : 0;
                int jj = __shfl_sync(hmask, j, half * 16 + tc);
                qr[u] = *(const uint2*)&g_Qh[jj * HDIM + hl * 4];
                vr[u] = *(const uint2*)&g_Vh[jj * HDIM + hl * 4];
                if (t >= m) { vr[u].x = 0u; vr[u].y = 0u; }   // zero v kills padding
            }
            #pragma unroll
            for (int u = 0; u < 4; u++) {
                float2 q01 = __half22float2(*(const __half2*)&qr[u].x);
                float2 q23 = __half22float2(*(const __half2*)&qr[u].y);
                float2 v01 = __half22float2(*(const __half2*)&vr[u].x);
                float2 v23 = __half22float2(*(const __half2*)&vr[u].y);
                ax = fmaf(gatef(q01.x, kh.x), v01.x, ax);
                ay = fmaf(gatef(q01.y, kh.y), v01.y, ay);
                az = fmaf(gatef(q23.x, kh.z), v23.x, az);
                aw = fmaf(gatef(q23.y, kh.w), v23.y, aw);
            }
        }
    }

    float4 sk = *(const float4*)&g_Sk[i * HDIM + hl * 4];
    ax += sk.x; ay += sk.y; az += sk.z; aw += sk.w;

    float4 w = *(const float4*)&Wsc[hl * 4];
    float p = ax * w.x + ay * w.y + az * w.z + aw * w.w;
    #pragma unroll
    for (int o = 8; o > 0; o >>= 1) p += __shfl_down_sync(hmask, p, o, 16);
    if (hl == 0) score[i] = p + bsc[0];
}

// ---------------- launch (kernel launches ONLY) ----------------
extern "C" void kernel_launch(void* const* d_in, const int* in_sizes, int n_in,
                              void* d_out, int out_size)
{
    const float* x     = (const float*)d_in[0];
    const void*  ei    = d_in[1];
    const float* W1    = (const float*)d_in[2];
    const float* b1    = (const float*)d_in[3];
    const float* W2    = (const float*)d_in[4];
    const float* b2    = (const float*)d_in[5];
    const float* Wk    = (const float*)d_in[6];
    const float* bk    = (const float*)d_in[7];
    const float* Wq    = (const float*)d_in[8];
    const float* bq    = (const float*)d_in[9];
    const float* Wv    = (const float*)d_in[10];
    const float* bv    = (const float*)d_in[11];
    const float* Ws    = (const float*)d_in[12];
    const float* bgate = (const float*)d_in[13];
    const float* Wsc   = (const float*)d_in[14];
    const float* bsc   = (const float*)d_in[15];
    float* score = (float*)d_out;

    init_kernel<<<(N_NODES + 255) / 256, 256>>>(ei);   // dtype probe + zero counts

    node_kernel<<<NUM_TILES, NTH>>>(x, W1, b1, W2, b2, Wk, bk,
                                    Wq, bq, Wv, bv, Ws, bgate, ei);

    scan_blocks_kernel<<<NBLK, SCAN_BLK>>>();
    final_scan_kernel<<<NBLK, SCAN_BLK>>>();
    scatter_kernel<<<(N_EDGES + 255) / 256, 256>>>(ei);

    int agg_blocks = (N_NODES / 2 * 32) / 256;   // 6250, exact
    aggregate_kernel<<<agg_blocks, 256>>>(Wsc, bsc, score);
}